// round 1
// baseline (speedup 1.0000x reference)
#include <cuda_runtime.h>
#include <math_constants.h>

// Grayscale morphological erosion, 5x5 SE, 'same' padding with +inf OOB.
// image: (32,3,1024,1024) fp32 -> 96 independent 1024x1024 planes.
//
// Tiling: each block covers a 128(W) x 64(H) output tile of one plane.
//   blockDim = (32, 8) = 256 threads
//   each thread computes CPT=4 columns (tx, tx+32, tx+64, tx+96) x RPT=8 rows.
// Shared tile: (64+4) x (128+4) input window, +inf-filled at image borders.
// Per thread: stream 12 input tile rows; each row's 5-wide register window
// feeds the (up to 5) output rows it overlaps -> 7.5 LDS per output instead
// of 25.

#define TILE_W 128
#define TILE_H 64
#define RPT 8
#define CPT 4
#define SW (TILE_W + 4)
#define SH (TILE_H + 4)

__global__ __launch_bounds__(256, 2)
void erosion5x5_kernel(const float* __restrict__ img,
                       const float* __restrict__ filt,
                       float* __restrict__ out)
{
    __shared__ float s[SH][SW];

    const int tx = threadIdx.x;
    const int ty = threadIdx.y;
    const int tid = ty * 32 + tx;
    const int plane = blockIdx.z;
    const int x0 = blockIdx.x * TILE_W;
    const int y0 = blockIdx.y * TILE_H;

    const float* __restrict__ base = img + (size_t)plane * (1024 * 1024);

    // Structuring element into registers (uniform broadcast loads, L1-hot).
    float f[25];
#pragma unroll
    for (int i = 0; i < 25; ++i) f[i] = __ldg(&filt[i]);

    // Cooperative tile fill with +inf border handling.
    const int total = SH * SW;
    for (int idx = tid; idx < total; idx += 256) {
        const int sy = idx / SW;
        const int sx = idx - sy * SW;
        const int gy = y0 + sy - 2;
        const int gx = x0 + sx - 2;
        float v = CUDART_INF_F;
        if ((unsigned)gy < 1024u && (unsigned)gx < 1024u)
            v = __ldg(&base[gy * 1024 + gx]);
        s[sy][sx] = v;
    }
    __syncthreads();

    float acc[RPT][CPT];
#pragma unroll
    for (int yy = 0; yy < RPT; ++yy)
#pragma unroll
        for (int c = 0; c < CPT; ++c)
            acc[yy][c] = CUDART_INF_F;

    const int rbase = ty * RPT;

    // Stream the 12 input rows this thread's 8 output rows depend on.
#pragma unroll
    for (int rr = 0; rr < RPT + 4; ++rr) {
#pragma unroll
        for (int c = 0; c < CPT; ++c) {
            const int col = tx + c * 32;  // lane-stride-1 -> conflict-free LDS
            const float w0 = s[rbase + rr][col + 0];
            const float w1 = s[rbase + rr][col + 1];
            const float w2 = s[rbase + rr][col + 2];
            const float w3 = s[rbase + rr][col + 3];
            const float w4 = s[rbase + rr][col + 4];
#pragma unroll
            for (int yy = 0; yy < RPT; ++yy) {
                const int i = rr - yy;   // SE row index for this output row
                if (i >= 0 && i < 5) {
                    float a = acc[yy][c];
                    a = fminf(a, w0 - f[i * 5 + 0]);
                    a = fminf(a, w1 - f[i * 5 + 1]);
                    a = fminf(a, w2 - f[i * 5 + 2]);
                    a = fminf(a, w3 - f[i * 5 + 3]);
                    a = fminf(a, w4 - f[i * 5 + 4]);
                    acc[yy][c] = a;
                }
            }
        }
    }

    // Coalesced stores; 1024 % 128 == 0 and 1024 % 64 == 0 -> no bounds checks.
    float* __restrict__ obase = out + (size_t)plane * (1024 * 1024);
#pragma unroll
    for (int yy = 0; yy < RPT; ++yy) {
        const int gy = y0 + rbase + yy;
#pragma unroll
        for (int c = 0; c < CPT; ++c) {
            const int gx = x0 + tx + c * 32;
            obase[(size_t)gy * 1024 + gx] = acc[yy][c];
        }
    }
}

extern "C" void kernel_launch(void* const* d_in, const int* in_sizes, int n_in,
                              void* d_out, int out_size)
{
    const float* img  = (const float*)d_in[0];   // (32,3,1024,1024) fp32
    const float* filt = (const float*)d_in[1];   // (5,5) fp32
    float* out = (float*)d_out;

    dim3 block(32, 8, 1);
    dim3 grid(1024 / TILE_W, 1024 / TILE_H, 32 * 3);
    erosion5x5_kernel<<<grid, block>>>(img, filt, out);
}